// round 1
// baseline (speedup 1.0000x reference)
#include <cuda_runtime.h>
#include <cuda_bf16.h>
#include <cstdint>

// Problem constants
#define BB   2
#define TT   260
#define HH   4
#define DD   1024
#define VV   32000
#define DFF  2048
#define NN   256            // T - H
#define MM   (BB * NN)      // 512 token rows

// ---------------------------------------------------------------------------
// Scratch (no allocations allowed -> __device__ globals)
// ---------------------------------------------------------------------------
__device__ float g_bufA[MM * DD];      // h_prev / x ping
__device__ float g_bufB[MM * DD];      // h_prev / x pong
__device__ float g_xc [MM * 2 * DD];   // concat(rms(e), rms(h_prev))
__device__ float g_t1 [MM * DFF];      // GEMM intermediate (wide)
__device__ float g_t2 [MM * DD];       // GEMM intermediate (narrow)

// ---------------------------------------------------------------------------
// Block-wide sum reduce (256 threads)
// ---------------------------------------------------------------------------
__device__ __forceinline__ float block_sum(float v) {
    __shared__ float sh[32];
    const int lane = threadIdx.x & 31;
    const int wid  = threadIdx.x >> 5;
    #pragma unroll
    for (int o = 16; o; o >>= 1) v += __shfl_xor_sync(0xffffffffu, v, o);
    if (lane == 0) sh[wid] = v;
    __syncthreads();
    if (wid == 0) {
        v = (lane < 8) ? sh[lane] : 0.0f;
        #pragma unroll
        for (int o = 4; o; o >>= 1) v += __shfl_xor_sync(0xffffffffu, v, o);
        if (lane == 0) sh[0] = v;
    }
    __syncthreads();
    v = sh[0];
    __syncthreads();
    return v;
}

// ---------------------------------------------------------------------------
// init: h_buf[m, :] = hidden_states[b, j, :]  (m = b*256 + j)
// ---------------------------------------------------------------------------
__global__ void init_h_kernel(const float* __restrict__ hidden, float* __restrict__ hbuf) {
    const int m = blockIdx.x;
    const int b = m >> 8, j = m & 255;
    const float* src = hidden + ((size_t)b * TT + j) * DD;
    float* dst = hbuf + (size_t)m * DD;
    #pragma unroll
    for (int i = 0; i < 4; i++) {
        const int d = threadIdx.x + i * 256;
        dst[d] = src[d];
    }
}

// ---------------------------------------------------------------------------
// prep: xc[m, 0:1024]    = rms(emb_table[tok[b, 1+h+j]])
//       xc[m, 1024:2048] = rms(h_prev[m])
// grid (512, 2), 256 threads
// ---------------------------------------------------------------------------
__global__ void prep_kernel(const int* __restrict__ tok,
                            const float* __restrict__ emb,
                            const float* __restrict__ hprev,
                            const float* __restrict__ rms_w,
                            float* __restrict__ xc, int h) {
    const int m = blockIdx.x;
    const int half = blockIdx.y;
    const int tid = threadIdx.x;
    const int b = m >> 8, j = m & 255;

    const float* src;
    if (half == 0) {
        const int t = tok[b * TT + 1 + h + j];
        src = emb + (size_t)t * DD;
    } else {
        src = hprev + (size_t)m * DD;
    }

    float v[4];
    float ss = 0.0f;
    #pragma unroll
    for (int i = 0; i < 4; i++) {
        v[i] = src[tid + i * 256];
        ss += v[i] * v[i];
    }
    ss = block_sum(ss);
    const float s = rsqrtf(ss * (1.0f / DD) + 1e-6f);

    float* dst = xc + (size_t)m * (2 * DD) + half * DD;
    #pragma unroll
    for (int i = 0; i < 4; i++) {
        const int d = tid + i * 256;
        dst[d] = v[i] * s * rms_w[d];
    }
}

// ---------------------------------------------------------------------------
// residual + LayerNorm (in place on x): x = ln(x + u) * w + b
// grid 512, 256 threads
// ---------------------------------------------------------------------------
__global__ void resid_ln_kernel(float* __restrict__ x, const float* __restrict__ u,
                                const float* __restrict__ w, const float* __restrict__ bb) {
    const int m = blockIdx.x;
    const int tid = threadIdx.x;
    float* xr = x + (size_t)m * DD;
    const float* ur = u + (size_t)m * DD;

    float v[4];
    float s = 0.0f;
    #pragma unroll
    for (int i = 0; i < 4; i++) {
        v[i] = xr[tid + i * 256] + ur[tid + i * 256];
        s += v[i];
    }
    s = block_sum(s);
    const float mu = s * (1.0f / DD);

    float s2 = 0.0f;
    #pragma unroll
    for (int i = 0; i < 4; i++) {
        const float d = v[i] - mu;
        s2 += d * d;
    }
    s2 = block_sum(s2);
    const float rs = rsqrtf(s2 * (1.0f / DD) + 1e-5f);

    #pragma unroll
    for (int i = 0; i < 4; i++) {
        const int d = tid + i * 256;
        xr[d] = (v[i] - mu) * rs * w[d] + bb[d];
    }
}

// ---------------------------------------------------------------------------
// NT GEMM, 64x64 tile (for small-N GEMMs): C[m,n] = sum_k A[m,k]*B[n,k] + bias[n]
// A: MxK row-major, B: NxK row-major, C row-major with leading dim ldc.
// 256 threads, TM=TN=4, BK=16. All dims divide tiles exactly.
// ---------------------------------------------------------------------------
__global__ void __launch_bounds__(256) gemm_nt_64(
    const float* __restrict__ A, const float* __restrict__ B,
    const float* __restrict__ bias, float* __restrict__ C,
    int K, int ldc, int relu)
{
    __shared__ float As[16][68];
    __shared__ float Bs[16][68];
    const int tid  = threadIdx.x;
    const int m0   = blockIdx.x * 64;
    const int n0   = blockIdx.y * 64;
    const int lrow = tid >> 2;           // 0..63
    const int lcol = (tid & 3) << 2;     // 0,4,8,12
    const int tm   = (tid >> 4) << 2;    // 0..60
    const int tn   = (tid & 15) << 2;    // 0..60

    float acc[4][4] = {};
    const float* Ap = A + (size_t)(m0 + lrow) * K + lcol;
    const float* Bp = B + (size_t)(n0 + lrow) * K + lcol;

    for (int kt = 0; kt < K; kt += 16) {
        const float4 va = *(const float4*)(Ap + kt);
        const float4 vb = *(const float4*)(Bp + kt);
        As[lcol + 0][lrow] = va.x; As[lcol + 1][lrow] = va.y;
        As[lcol + 2][lrow] = va.z; As[lcol + 3][lrow] = va.w;
        Bs[lcol + 0][lrow] = vb.x; Bs[lcol + 1][lrow] = vb.y;
        Bs[lcol + 2][lrow] = vb.z; Bs[lcol + 3][lrow] = vb.w;
        __syncthreads();
        #pragma unroll
        for (int k = 0; k < 16; k++) {
            float a[4], bq[4];
            #pragma unroll
            for (int i = 0; i < 4; i++) a[i]  = As[k][tm + i];
            #pragma unroll
            for (int i = 0; i < 4; i++) bq[i] = Bs[k][tn + i];
            #pragma unroll
            for (int i = 0; i < 4; i++)
                #pragma unroll
                for (int jj = 0; jj < 4; jj++)
                    acc[i][jj] = fmaf(a[i], bq[jj], acc[i][jj]);
        }
        __syncthreads();
    }

    #pragma unroll
    for (int i = 0; i < 4; i++) {
        float* Cr = C + (size_t)(m0 + tm + i) * ldc + n0 + tn;
        #pragma unroll
        for (int jj = 0; jj < 4; jj++) {
            float v = acc[i][jj] + bias[n0 + tn + jj];
            if (relu) v = fmaxf(v, 0.0f);
            Cr[jj] = v;
        }
    }
}

// ---------------------------------------------------------------------------
// NT GEMM, 128x128 tile (for the unembed GEMM). 256 threads, TM=TN=8, BK=16.
// ---------------------------------------------------------------------------
__global__ void __launch_bounds__(256) gemm_nt_128(
    const float* __restrict__ A, const float* __restrict__ B,
    const float* __restrict__ bias, float* __restrict__ C,
    int K, long ldc)
{
    __shared__ float As[16][132];
    __shared__ float Bs[16][132];
    const int tid  = threadIdx.x;
    const int m0   = blockIdx.x * 128;
    const int n0   = blockIdx.y * 128;
    const int lrow = tid >> 2;           // 0..63
    const int lcol = (tid & 3) << 2;     // 0,4,8,12
    const int tm   = (tid >> 4) << 3;    // 0..120
    const int tn   = (tid & 15) << 3;    // 0..120

    float acc[8][8] = {};
    const float* Ap = A + (size_t)(m0 + lrow) * K + lcol;
    const float* Bp = B + (size_t)(n0 + lrow) * K + lcol;

    for (int kt = 0; kt < K; kt += 16) {
        #pragma unroll
        for (int i = 0; i < 2; i++) {
            const float4 va = *(const float4*)(Ap + (size_t)i * 64 * K + kt);
            As[lcol + 0][lrow + i * 64] = va.x; As[lcol + 1][lrow + i * 64] = va.y;
            As[lcol + 2][lrow + i * 64] = va.z; As[lcol + 3][lrow + i * 64] = va.w;
            const float4 vb = *(const float4*)(Bp + (size_t)i * 64 * K + kt);
            Bs[lcol + 0][lrow + i * 64] = vb.x; Bs[lcol + 1][lrow + i * 64] = vb.y;
            Bs[lcol + 2][lrow + i * 64] = vb.z; Bs[lcol + 3][lrow + i * 64] = vb.w;
        }
        __syncthreads();
        #pragma unroll
        for (int k = 0; k < 16; k++) {
            float a[8], bq[8];
            #pragma unroll
            for (int i = 0; i < 8; i++) a[i]  = As[k][tm + i];
            #pragma unroll
            for (int i = 0; i < 8; i++) bq[i] = Bs[k][tn + i];
            #pragma unroll
            for (int i = 0; i < 8; i++)
                #pragma unroll
                for (int jj = 0; jj < 8; jj++)
                    acc[i][jj] = fmaf(a[i], bq[jj], acc[i][jj]);
        }
        __syncthreads();
    }

    #pragma unroll
    for (int i = 0; i < 8; i++) {
        float* Cr = C + (size_t)(m0 + tm + i) * ldc + n0 + tn;
        #pragma unroll
        for (int jj = 0; jj < 8; jj++) {
            Cr[jj] = acc[i][jj] + bias[n0 + tn + jj];
        }
    }
}

// ---------------------------------------------------------------------------
// Host-side orchestration
// ---------------------------------------------------------------------------
extern "C" void kernel_launch(void* const* d_in, const int* in_sizes, int n_in,
                              void* d_out, int out_size) {
    const int*   tok      = (const int*)  d_in[0];
    const float* hidden   = (const float*)d_in[1];
    const float* emb      = (const float*)d_in[2];
    const float* rms_w    = (const float*)d_in[3];
    const float* proj_w   = (const float*)d_in[4];
    const float* proj_b   = (const float*)d_in[5];
    const float* sa_wv    = (const float*)d_in[6];
    const float* sa_bv    = (const float*)d_in[7];
    const float* sa_wo    = (const float*)d_in[8];
    const float* sa_bo    = (const float*)d_in[9];
    const float* ca_wv    = (const float*)d_in[10];
    const float* ca_bv    = (const float*)d_in[11];
    const float* ca_wo    = (const float*)d_in[12];
    const float* ca_bo    = (const float*)d_in[13];
    const float* ln1_w    = (const float*)d_in[14];
    const float* ln1_b    = (const float*)d_in[15];
    const float* ln2_w    = (const float*)d_in[16];
    const float* ln2_b    = (const float*)d_in[17];
    const float* ln3_w    = (const float*)d_in[18];
    const float* ln3_b    = (const float*)d_in[19];
    const float* ff_w1    = (const float*)d_in[20];
    const float* ff_b1    = (const float*)d_in[21];
    const float* ff_w2    = (const float*)d_in[22];
    const float* ff_b2    = (const float*)d_in[23];
    const float* unemb_w  = (const float*)d_in[24];
    const float* unemb_b  = (const float*)d_in[25];
    float* out = (float*)d_out;

    static float *bufA = nullptr, *bufB = nullptr, *xc = nullptr, *t1 = nullptr, *t2 = nullptr;
    if (!bufA) {
        cudaGetSymbolAddress((void**)&bufA, g_bufA);
        cudaGetSymbolAddress((void**)&bufB, g_bufB);
        cudaGetSymbolAddress((void**)&xc,  g_xc);
        cudaGetSymbolAddress((void**)&t1,  g_t1);
        cudaGetSymbolAddress((void**)&t2,  g_t2);
    }

    init_h_kernel<<<MM, 256>>>(hidden, bufA);

    for (int h = 0; h < HH; h++) {
        float* hprev = (h & 1) ? bufB : bufA;
        float* x     = (h & 1) ? bufA : bufB;

        // xc = concat(rms(e), rms(h_prev))
        prep_kernel<<<dim3(MM, 2), 256>>>(tok, emb, hprev, rms_w, xc, h);

        // x = xc @ proj_w[h]^T + proj_b[h]   (M=512, N=1024, K=2048)
        gemm_nt_64<<<dim3(MM / 64, DD / 64), 256>>>(
            xc, proj_w + (size_t)h * DD * 2 * DD, proj_b + (size_t)h * DD, x,
            2 * DD, DD, 0);

        // "self-attn": x = ln1(x + (x@wv^T+bv)@wo^T+bo)
        gemm_nt_64<<<dim3(MM / 64, DD / 64), 256>>>(
            x, sa_wv + (size_t)h * DD * DD, sa_bv + (size_t)h * DD, t1, DD, DD, 0);
        gemm_nt_64<<<dim3(MM / 64, DD / 64), 256>>>(
            t1, sa_wo + (size_t)h * DD * DD, sa_bo + (size_t)h * DD, t2, DD, DD, 0);
        resid_ln_kernel<<<MM, 256>>>(x, t2, ln1_w + (size_t)h * DD, ln1_b + (size_t)h * DD);

        // "cross-attn": x = ln2(x + (x@wv2^T+bv2)@wo2^T+bo2)
        gemm_nt_64<<<dim3(MM / 64, DD / 64), 256>>>(
            x, ca_wv + (size_t)h * DD * DD, ca_bv + (size_t)h * DD, t1, DD, DD, 0);
        gemm_nt_64<<<dim3(MM / 64, DD / 64), 256>>>(
            t1, ca_wo + (size_t)h * DD * DD, ca_bo + (size_t)h * DD, t2, DD, DD, 0);
        resid_ln_kernel<<<MM, 256>>>(x, t2, ln2_w + (size_t)h * DD, ln2_b + (size_t)h * DD);

        // FFN: x = ln3(x + relu(x@f1^T+b1)@f2^T+b2)
        gemm_nt_64<<<dim3(MM / 64, DFF / 64), 256>>>(
            x, ff_w1 + (size_t)h * DFF * DD, ff_b1 + (size_t)h * DFF, t1, DD, DFF, 1);
        gemm_nt_64<<<dim3(MM / 64, DD / 64), 256>>>(
            t1, ff_w2 + (size_t)h * DD * DFF, ff_b2 + (size_t)h * DD, t2, DFF, DD, 0);
        resid_ln_kernel<<<MM, 256>>>(x, t2, ln3_w + (size_t)h * DD, ln3_b + (size_t)h * DD);

        // logits: out[b, j, h, :] = x[m] @ unemb_w^T + unemb_b
        gemm_nt_128<<<dim3(MM / 128, VV / 128), 256>>>(
            x, unemb_w, unemb_b, out + (size_t)h * VV, DD, (long)HH * VV);
    }
}

// round 4
// speedup vs baseline: 2.1889x; 2.1889x over previous
#include <cuda_runtime.h>
#include <cuda_bf16.h>
#include <cstdint>

// Problem constants
#define BB   2
#define TT   260
#define HH   4
#define DD   1024
#define VV   32000
#define DFF  2048
#define MM   512            // B * (T - H) token rows

// ---------------------------------------------------------------------------
// Scratch (__device__ globals; no allocations allowed)
// ---------------------------------------------------------------------------
__device__ float g_bufA[MM * DD];
__device__ float g_bufB[MM * DD];
__device__ float g_xc [MM * 2 * DD];
__device__ float g_t1 [MM * DFF];
__device__ float g_t2 [MM * DD];

// ---------------------------------------------------------------------------
// helpers
// ---------------------------------------------------------------------------
__device__ __forceinline__ float block_sum(float v) {
    __shared__ float sh[32];
    const int lane = threadIdx.x & 31;
    const int wid  = threadIdx.x >> 5;
    #pragma unroll
    for (int o = 16; o; o >>= 1) v += __shfl_xor_sync(0xffffffffu, v, o);
    if (lane == 0) sh[wid] = v;
    __syncthreads();
    if (wid == 0) {
        v = (lane < 8) ? sh[lane] : 0.0f;
        #pragma unroll
        for (int o = 4; o; o >>= 1) v += __shfl_xor_sync(0xffffffffu, v, o);
        if (lane == 0) sh[0] = v;
    }
    __syncthreads();
    v = sh[0];
    __syncthreads();
    return v;
}

__global__ void init_h_kernel(const float* __restrict__ hidden, float* __restrict__ hbuf) {
    const int m = blockIdx.x;
    const int b = m >> 8, j = m & 255;
    const float* src = hidden + ((size_t)b * TT + j) * DD;
    float* dst = hbuf + (size_t)m * DD;
    #pragma unroll
    for (int i = 0; i < 4; i++) dst[threadIdx.x + i * 256] = src[threadIdx.x + i * 256];
}

__global__ void prep_kernel(const int* __restrict__ tok,
                            const float* __restrict__ emb,
                            const float* __restrict__ hprev,
                            const float* __restrict__ rms_w,
                            float* __restrict__ xc, int h) {
    const int m = blockIdx.x;
    const int half = blockIdx.y;
    const int tid = threadIdx.x;
    const int b = m >> 8, j = m & 255;
    const float* src;
    if (half == 0) {
        const int t = tok[b * TT + 1 + h + j];
        src = emb + (size_t)t * DD;
    } else {
        src = hprev + (size_t)m * DD;
    }
    float v[4];
    float ss = 0.0f;
    #pragma unroll
    for (int i = 0; i < 4; i++) { v[i] = src[tid + i * 256]; ss += v[i] * v[i]; }
    ss = block_sum(ss);
    const float s = rsqrtf(ss * (1.0f / DD) + 1e-6f);
    float* dst = xc + (size_t)m * (2 * DD) + half * DD;
    #pragma unroll
    for (int i = 0; i < 4; i++) {
        const int d = tid + i * 256;
        dst[d] = v[i] * s * rms_w[d];
    }
}

__global__ void resid_ln_kernel(float* __restrict__ x, const float* __restrict__ u,
                                const float* __restrict__ w, const float* __restrict__ bb) {
    const int m = blockIdx.x;
    const int tid = threadIdx.x;
    float* xr = x + (size_t)m * DD;
    const float* ur = u + (size_t)m * DD;
    float v[4];
    float s = 0.0f;
    #pragma unroll
    for (int i = 0; i < 4; i++) {
        v[i] = xr[tid + i * 256] + ur[tid + i * 256];
        s += v[i];
    }
    s = block_sum(s);
    const float mu = s * (1.0f / DD);
    float s2 = 0.0f;
    #pragma unroll
    for (int i = 0; i < 4; i++) { const float d = v[i] - mu; s2 += d * d; }
    s2 = block_sum(s2);
    const float rs = rsqrtf(s2 * (1.0f / DD) + 1e-5f);
    #pragma unroll
    for (int i = 0; i < 4; i++) {
        const int d = tid + i * 256;
        xr[d] = (v[i] - mu) * rs * w[d] + bb[d];
    }
}

// ---------------------------------------------------------------------------
// mma.sync bf16 split-precision GEMM (HMMA path; tcgen05 unavailable on this
// toolchain's compute_103 virtual arch).
// C[m,n] = sum_k A[m,k]*B[n,k] + bias[n].  A: MxK fp32 RM, B: NxK fp32 RM.
// Emulated fp32: acc += Ahi*Bhi + Ahi*Blo + Alo*Bhi (bf16 hi/lo, f32 acc).
// ---------------------------------------------------------------------------
__device__ __forceinline__ uint32_t s2u(const void* p) {
    uint32_t a;
    asm("{ .reg .u64 t; cvta.to.shared.u64 t, %1; cvt.u32.u64 %0, t; }" : "=r"(a) : "l"(p));
    return a;
}
__device__ __forceinline__ void ldsm4(uint32_t* r, uint32_t addr) {
    asm volatile("ldmatrix.sync.aligned.m8n8.x4.shared.b16 {%0,%1,%2,%3}, [%4];"
                 : "=r"(r[0]), "=r"(r[1]), "=r"(r[2]), "=r"(r[3]) : "r"(addr));
}
__device__ __forceinline__ void mma_bf16(float* c, const uint32_t* a, const uint32_t* b) {
    asm volatile(
        "mma.sync.aligned.m16n8k16.row.col.f32.bf16.bf16.f32 "
        "{%0,%1,%2,%3}, {%4,%5,%6,%7}, {%8,%9}, {%0,%1,%2,%3};"
        : "+f"(c[0]), "+f"(c[1]), "+f"(c[2]), "+f"(c[3])
        : "r"(a[0]), "r"(a[1]), "r"(a[2]), "r"(a[3]), "r"(b[0]), "r"(b[1]));
}
__device__ __forceinline__ uint32_t pack_bf2(float lo, float hi) {
    __nv_bfloat162 p = __floats2bfloat162_rn(lo, hi);   // .x = lo halfword
    return *reinterpret_cast<uint32_t*>(&p);
}

// BM x BN tile, 256 threads (8 warps, WGM x WGN = (8/WGN) x WGN),
// BK = 32 bf16, double-buffered SMEM, padded stride 40 elems (80B rows).
template<int BM, int BN, int WGN>
__global__ void __launch_bounds__(256) gemm_mma(
    const float* __restrict__ A, const float* __restrict__ B,
    const float* __restrict__ bias, float* __restrict__ C,
    int K, long long ldc, int relu)
{
    constexpr int WGM = 8 / WGN;
    constexpr int WM  = BM / WGM;         // 32
    constexpr int WN  = BN / WGN;         // 64 (A-cfg) or 16 (B-cfg)
    constexpr int MI  = WM / 16;          // 2
    constexpr int NI  = WN / 8;           // 8 or 2
    constexpr int LS  = 40;               // padded elems per SMEM row
    constexpr int ATILE_B = BM * LS * 2;  // bytes per bf16 tile (A)
    constexpr int BTILE_B = BN * LS * 2;
    constexpr int STAGE_B = 2 * ATILE_B + 2 * BTILE_B;
    constexpr int A_F4 = BM / 32;         // float4 GMEM loads per thread (A)
    constexpr int B_F4 = BN / 32;

    extern __shared__ char smem[];
    const uint32_t sb = s2u(smem);

    const int tid  = threadIdx.x;
    const int wid  = tid >> 5;
    const int lane = tid & 31;
    const int wm   = wid / WGN;
    const int wn   = wid % WGN;
    const int m0   = blockIdx.x * BM;
    const int n0   = blockIdx.y * BN;

    float acc[MI][NI][4];
    #pragma unroll
    for (int i = 0; i < MI; i++)
        #pragma unroll
        for (int j = 0; j < NI; j++)
            #pragma unroll
            for (int q = 0; q < 4; q++) acc[i][j][q] = 0.0f;

    // per-thread GMEM coords (row-major, 8 float4 per row of 32 floats)
    int arow[A_F4], acol[A_F4], brow[B_F4], bcol[B_F4];
    #pragma unroll
    for (int i = 0; i < A_F4; i++) { int idx = tid + i * 256; arow[i] = idx >> 3; acol[i] = (idx & 7) << 2; }
    #pragma unroll
    for (int i = 0; i < B_F4; i++) { int idx = tid + i * 256; brow[i] = idx >> 3; bcol[i] = (idx & 7) << 2; }

    const int nCh = K >> 5;
    float4 ra[A_F4], rb[B_F4];

    // ---- prologue: load + store chunk 0
    #pragma unroll
    for (int i = 0; i < A_F4; i++) ra[i] = *(const float4*)(A + (size_t)(m0 + arow[i]) * K + acol[i]);
    #pragma unroll
    for (int i = 0; i < B_F4; i++) rb[i] = *(const float4*)(B + (size_t)(n0 + brow[i]) * K + bcol[i]);

    #pragma unroll
    for (int st = 0; st < 1; st++) { } // (keep structure flat)

    {
        const uint32_t sAh = sb;
        const uint32_t sAl = sAh + ATILE_B;
        const uint32_t sBh = sAl + ATILE_B;
        const uint32_t sBl = sBh + BTILE_B;
        #pragma unroll
        for (int i = 0; i < A_F4; i++) {
            float f[4] = { ra[i].x, ra[i].y, ra[i].z, ra[i].w };
            float hf[4], lf[4];
            #pragma unroll
            for (int q = 0; q < 4; q++) {
                hf[q] = __bfloat162float(__float2bfloat16_rn(f[q]));
                lf[q] = f[q] - hf[q];
            }
            uint32_t off = (uint32_t)(arow[i] * LS + acol[i]) * 2u;
            uint32_t h0 = pack_bf2(hf[0], hf[1]), h1 = pack_bf2(hf[2], hf[3]);
            uint32_t l0 = pack_bf2(lf[0], lf[1]), l1 = pack_bf2(lf[2], lf[3]);
            asm volatile("st.shared.v2.b32 [%0], {%1,%2};" :: "r"(sAh + off), "r"(h0), "r"(h1));
            asm volatile("st.shared.v2.b32 [%0], {%1,%2};" :: "r"(sAl + off), "r"(l0), "r"(l1));
        }
        #pragma unroll
        for (int i = 0; i < B_F4; i++) {
            float f[4] = { rb[i].x, rb[i].y, rb[i].z, rb[i].w };
            float hf[4], lf[4];
            #pragma unroll
            for (int q = 0; q < 4; q++) {
                hf[q] = __bfloat162float(__float2bfloat16_rn(f[q]));
                lf[q] = f[q] - hf[q];
            }
            uint32_t off = (uint32_t)(brow[i] * LS + bcol[i]) * 2u;
            uint32_t h0 = pack_bf2(hf[0], hf[1]), h1 = pack_bf2(hf[2], hf[3]);
            uint32_t l0 = pack_bf2(lf[0], lf[1]), l1 = pack_bf2(lf[2], lf[3]);
            asm volatile("st.shared.v2.b32 [%0], {%1,%2};" :: "r"(sBh + off), "r"(h0), "r"(h1));
            asm volatile("st.shared.v2.b32 [%0], {%1,%2};" :: "r"(sBl + off), "r"(l0), "r"(l1));
        }
    }
    __syncthreads();

    // ---- main loop
    for (int c = 0; c < nCh; c++) {
        const bool more = (c + 1 < nCh);
        if (more) {
            const int k0 = (c + 1) << 5;
            #pragma unroll
            for (int i = 0; i < A_F4; i++) ra[i] = *(const float4*)(A + (size_t)(m0 + arow[i]) * K + k0 + acol[i]);
            #pragma unroll
            for (int i = 0; i < B_F4; i++) rb[i] = *(const float4*)(B + (size_t)(n0 + brow[i]) * K + k0 + bcol[i]);
        }

        // MMA on stage c&1
        {
            const uint32_t stage = sb + (uint32_t)(c & 1) * STAGE_B;
            const uint32_t sAh = stage;
            const uint32_t sBh = stage + 2 * ATILE_B;
            #pragma unroll
            for (int ks = 0; ks < 2; ks++) {
                uint32_t ah[MI][4], al[MI][4];
                #pragma unroll
                for (int mi = 0; mi < MI; mi++) {
                    const int row = wm * WM + mi * 16 + (lane & 15);
                    const int col = ks * 16 + (lane >> 4) * 8;
                    const uint32_t ad = sAh + (uint32_t)(row * LS + col) * 2u;
                    ldsm4(ah[mi], ad);
                    ldsm4(al[mi], ad + ATILE_B);
                }
                uint32_t bh[NI][2], bl[NI][2];
                #pragma unroll
                for (int ni = 0; ni < NI; ni += 2) {
                    const int g = lane >> 3;                     // 0..3
                    const int row = wn * WN + ni * 8 + ((g >> 1) << 3) + (lane & 7);
                    const int col = ks * 16 + ((g & 1) << 3);
                    const uint32_t bd = sBh + (uint32_t)(row * LS + col) * 2u;
                    ldsm4(&bh[ni][0], bd);
                    ldsm4(&bl[ni][0], bd + BTILE_B);
                }
                #pragma unroll
                for (int mi = 0; mi < MI; mi++)
                    #pragma unroll
                    for (int ni = 0; ni < NI; ni++)
                        mma_bf16(acc[mi][ni], ah[mi], bh[ni]);
                #pragma unroll
                for (int mi = 0; mi < MI; mi++)
                    #pragma unroll
                    for (int ni = 0; ni < NI; ni++)
                        mma_bf16(acc[mi][ni], ah[mi], bl[ni]);
                #pragma unroll
                for (int mi = 0; mi < MI; mi++)
                    #pragma unroll
                    for (int ni = 0; ni < NI; ni++)
                        mma_bf16(acc[mi][ni], al[mi], bh[ni]);
            }
        }

        if (more) {
            const uint32_t stage = sb + (uint32_t)((c + 1) & 1) * STAGE_B;
            const uint32_t sAh = stage;
            const uint32_t sAl = sAh + ATILE_B;
            const uint32_t sBh = sAl + ATILE_B;
            const uint32_t sBl = sBh + BTILE_B;
            #pragma unroll
            for (int i = 0; i < A_F4; i++) {
                float f[4] = { ra[i].x, ra[i].y, ra[i].z, ra[i].w };
                float hf[4], lf[4];
                #pragma unroll
                for (int q = 0; q < 4; q++) {
                    hf[q] = __bfloat162float(__float2bfloat16_rn(f[q]));
                    lf[q] = f[q] - hf[q];
                }
                uint32_t off = (uint32_t)(arow[i] * LS + acol[i]) * 2u;
                uint32_t h0 = pack_bf2(hf[0], hf[1]), h1 = pack_bf2(hf[2], hf[3]);
                uint32_t l0 = pack_bf2(lf[0], lf[1]), l1 = pack_bf2(lf[2], lf[3]);
                asm volatile("st.shared.v2.b32 [%0], {%1,%2};" :: "r"(sAh + off), "r"(h0), "r"(h1));
                asm volatile("st.shared.v2.b32 [%0], {%1,%2};" :: "r"(sAl + off), "r"(l0), "r"(l1));
            }
            #pragma unroll
            for (int i = 0; i < B_F4; i++) {
                float f[4] = { rb[i].x, rb[i].y, rb[i].z, rb[i].w };
                float hf[4], lf[4];
                #pragma unroll
                for (int q = 0; q < 4; q++) {
                    hf[q] = __bfloat162float(__float2bfloat16_rn(f[q]));
                    lf[q] = f[q] - hf[q];
                }
                uint32_t off = (uint32_t)(brow[i] * LS + bcol[i]) * 2u;
                uint32_t h0 = pack_bf2(hf[0], hf[1]), h1 = pack_bf2(hf[2], hf[3]);
                uint32_t l0 = pack_bf2(lf[0], lf[1]), l1 = pack_bf2(lf[2], lf[3]);
                asm volatile("st.shared.v2.b32 [%0], {%1,%2};" :: "r"(sBh + off), "r"(h0), "r"(h1));
                asm volatile("st.shared.v2.b32 [%0], {%1,%2};" :: "r"(sBl + off), "r"(l0), "r"(l1));
            }
        }
        __syncthreads();
    }

    // ---- epilogue
    #pragma unroll
    for (int mi = 0; mi < MI; mi++) {
        #pragma unroll
        for (int ni = 0; ni < NI; ni++) {
            const int r0 = m0 + wm * WM + mi * 16 + (lane >> 2);
            const int cc = n0 + wn * WN + ni * 8 + ((lane & 3) << 1);
            const float b0 = bias[cc], b1 = bias[cc + 1];
            float v0 = acc[mi][ni][0] + b0;
            float v1 = acc[mi][ni][1] + b1;
            float v2 = acc[mi][ni][2] + b0;
            float v3 = acc[mi][ni][3] + b1;
            if (relu) {
                v0 = fmaxf(v0, 0.0f); v1 = fmaxf(v1, 0.0f);
                v2 = fmaxf(v2, 0.0f); v3 = fmaxf(v3, 0.0f);
            }
            float2* p0 = (float2*)(C + (size_t)r0 * (size_t)ldc + cc);
            float2* p1 = (float2*)(C + (size_t)(r0 + 8) * (size_t)ldc + cc);
            *p0 = make_float2(v0, v1);
            *p1 = make_float2(v2, v3);
        }
    }
}

// SMEM sizes per config
#define SMEM_BIG   (2 * (2 * 128 * 40 * 2 + 2 * 128 * 40 * 2))   // 81920
#define SMEM_SMALL (2 * (2 * 64 * 40 * 2 + 2 * 64 * 40 * 2))     // 40960

// ---------------------------------------------------------------------------
// Host orchestration
// ---------------------------------------------------------------------------
extern "C" void kernel_launch(void* const* d_in, const int* in_sizes, int n_in,
                              void* d_out, int out_size) {
    const int*   tok     = (const int*)  d_in[0];
    const float* hidden  = (const float*)d_in[1];
    const float* emb     = (const float*)d_in[2];
    const float* rms_w   = (const float*)d_in[3];
    const float* proj_w  = (const float*)d_in[4];
    const float* proj_b  = (const float*)d_in[5];
    const float* sa_wv   = (const float*)d_in[6];
    const float* sa_bv   = (const float*)d_in[7];
    const float* sa_wo   = (const float*)d_in[8];
    const float* sa_bo   = (const float*)d_in[9];
    const float* ca_wv   = (const float*)d_in[10];
    const float* ca_bv   = (const float*)d_in[11];
    const float* ca_wo   = (const float*)d_in[12];
    const float* ca_bo   = (const float*)d_in[13];
    const float* ln1_w   = (const float*)d_in[14];
    const float* ln1_b   = (const float*)d_in[15];
    const float* ln2_w   = (const float*)d_in[16];
    const float* ln2_b   = (const float*)d_in[17];
    const float* ln3_w   = (const float*)d_in[18];
    const float* ln3_b   = (const float*)d_in[19];
    const float* ff_w1   = (const float*)d_in[20];
    const float* ff_b1   = (const float*)d_in[21];
    const float* ff_w2   = (const float*)d_in[22];
    const float* ff_b2   = (const float*)d_in[23];
    const float* unemb_w = (const float*)d_in[24];
    const float* unemb_b = (const float*)d_in[25];
    float* out = (float*)d_out;

    static float *bufA = nullptr, *bufB = nullptr, *xc = nullptr, *t1 = nullptr, *t2 = nullptr;
    static bool attr_done = false;
    if (!bufA) {
        cudaGetSymbolAddress((void**)&bufA, g_bufA);
        cudaGetSymbolAddress((void**)&bufB, g_bufB);
        cudaGetSymbolAddress((void**)&xc,  g_xc);
        cudaGetSymbolAddress((void**)&t1,  g_t1);
        cudaGetSymbolAddress((void**)&t2,  g_t2);
    }
    if (!attr_done) {
        cudaFuncSetAttribute(gemm_mma<128, 128, 2>,
                             cudaFuncAttributeMaxDynamicSharedMemorySize, SMEM_BIG);
        attr_done = true;
    }

    init_h_kernel<<<MM, 256>>>(hidden, bufA);

    for (int h = 0; h < HH; h++) {
        float* hprev = (h & 1) ? bufB : bufA;
        float* x     = (h & 1) ? bufA : bufB;

        prep_kernel<<<dim3(MM, 2), 256>>>(tok, emb, hprev, rms_w, xc, h);

        // x = xc @ proj_w[h]^T + proj_b[h]   (512 x 1024 x 2048)
        gemm_mma<64, 64, 4><<<dim3(MM / 64, DD / 64), 256, SMEM_SMALL>>>(
            xc, proj_w + (size_t)h * DD * 2 * DD, proj_b + (size_t)h * DD, x,
            2 * DD, DD, 0);

        gemm_mma<64, 64, 4><<<dim3(MM / 64, DD / 64), 256, SMEM_SMALL>>>(
            x, sa_wv + (size_t)h * DD * DD, sa_bv + (size_t)h * DD, t1, DD, DD, 0);
        gemm_mma<64, 64, 4><<<dim3(MM / 64, DD / 64), 256, SMEM_SMALL>>>(
            t1, sa_wo + (size_t)h * DD * DD, sa_bo + (size_t)h * DD, t2, DD, DD, 0);
        resid_ln_kernel<<<MM, 256>>>(x, t2, ln1_w + (size_t)h * DD, ln1_b + (size_t)h * DD);

        gemm_mma<64, 64, 4><<<dim3(MM / 64, DD / 64), 256, SMEM_SMALL>>>(
            x, ca_wv + (size_t)h * DD * DD, ca_bv + (size_t)h * DD, t1, DD, DD, 0);
        gemm_mma<64, 64, 4><<<dim3(MM / 64, DD / 64), 256, SMEM_SMALL>>>(
            t1, ca_wo + (size_t)h * DD * DD, ca_bo + (size_t)h * DD, t2, DD, DD, 0);
        resid_ln_kernel<<<MM, 256>>>(x, t2, ln2_w + (size_t)h * DD, ln2_b + (size_t)h * DD);

        gemm_mma<64, 64, 4><<<dim3(MM / 64, DFF / 64), 256, SMEM_SMALL>>>(
            x, ff_w1 + (size_t)h * DFF * DD, ff_b1 + (size_t)h * DFF, t1, DD, DFF, 1);
        gemm_mma<64, 64, 4><<<dim3(MM / 64, DD / 64), 256, SMEM_SMALL>>>(
            t1, ff_w2 + (size_t)h * DD * DFF, ff_b2 + (size_t)h * DD, t2, DFF, DD, 0);
        resid_ln_kernel<<<MM, 256>>>(x, t2, ln3_w + (size_t)h * DD, ln3_b + (size_t)h * DD);

        // logits: out[b, j, h, :] = x @ unemb_w^T + unemb_b   (512 x 32000 x 1024)
        gemm_mma<128, 128, 2><<<dim3(MM / 128, VV / 128), 256, SMEM_BIG>>>(
            x, unemb_w, unemb_b, out + (size_t)h * VV, DD, (long long)HH * VV, 0);
    }
}

// round 5
// speedup vs baseline: 2.7190x; 1.2422x over previous
#include <cuda_runtime.h>
#include <cuda_bf16.h>
#include <cstdint>

// Problem constants
#define BB   2
#define TT   260
#define HH   4
#define DD   1024
#define VV   32000
#define DFF  2048
#define MM   512

// ---------------------------------------------------------------------------
// Persistent scratch (__device__ globals; no allocations allowed)
// ---------------------------------------------------------------------------
// Pre-converted bf16 hi/lo weights, one flat arena (offsets in elements)
#define OFF_PROJ 0
#define OFF_SAWV 8388608
#define OFF_SAWO 12582912
#define OFF_CAWV 16777216
#define OFF_CAWO 20971520
#define OFF_FF1  25165824
#define OFF_FF2  33554432
#define OFF_UNE  41943040
#define W_TOTAL  74711040

__device__ __nv_bfloat16 g_whi[W_TOTAL];
__device__ __nv_bfloat16 g_wlo[W_TOTAL];

__device__ float g_x  [MM * DD];      // fp32 hidden state (in-place across stages)
__device__ float g_t2 [MM * DD];      // fp32 GEMM output feeding resid_ln
__device__ __nv_bfloat16 g_xc_hi[MM * 2 * DD], g_xc_lo[MM * 2 * DD];
__device__ __nv_bfloat16 g_x_hi [MM * DD],     g_x_lo [MM * DD];
__device__ __nv_bfloat16 g_t1_hi[MM * DFF],    g_t1_lo[MM * DFF];

// ---------------------------------------------------------------------------
// helpers
// ---------------------------------------------------------------------------
__device__ __forceinline__ float block_sum(float v) {
    __shared__ float sh[32];
    const int lane = threadIdx.x & 31;
    const int wid  = threadIdx.x >> 5;
    #pragma unroll
    for (int o = 16; o; o >>= 1) v += __shfl_xor_sync(0xffffffffu, v, o);
    if (lane == 0) sh[wid] = v;
    __syncthreads();
    if (wid == 0) {
        v = (lane < 8) ? sh[lane] : 0.0f;
        #pragma unroll
        for (int o = 4; o; o >>= 1) v += __shfl_xor_sync(0xffffffffu, v, o);
        if (lane == 0) sh[0] = v;
    }
    __syncthreads();
    v = sh[0];
    __syncthreads();
    return v;
}

__device__ __forceinline__ uint32_t s2u(const void* p) {
    uint32_t a;
    asm("{ .reg .u64 t; cvta.to.shared.u64 t, %1; cvt.u32.u64 %0, t; }" : "=r"(a) : "l"(p));
    return a;
}
__device__ __forceinline__ void ldsm4(uint32_t* r, uint32_t addr) {
    asm volatile("ldmatrix.sync.aligned.m8n8.x4.shared.b16 {%0,%1,%2,%3}, [%4];"
                 : "=r"(r[0]), "=r"(r[1]), "=r"(r[2]), "=r"(r[3]) : "r"(addr));
}
__device__ __forceinline__ void mma_bf16(float* c, const uint32_t* a, const uint32_t* b) {
    asm volatile(
        "mma.sync.aligned.m16n8k16.row.col.f32.bf16.bf16.f32 "
        "{%0,%1,%2,%3}, {%4,%5,%6,%7}, {%8,%9}, {%0,%1,%2,%3};"
        : "+f"(c[0]), "+f"(c[1]), "+f"(c[2]), "+f"(c[3])
        : "r"(a[0]), "r"(a[1]), "r"(a[2]), "r"(a[3]), "r"(b[0]), "r"(b[1]));
}
__device__ __forceinline__ uint32_t pack_bf2(float a, float b) {
    __nv_bfloat162 p = __floats2bfloat162_rn(a, b);
    return *reinterpret_cast<uint32_t*>(&p);
}
__device__ __forceinline__ void split_bf(float f, __nv_bfloat16& h, __nv_bfloat16& l) {
    h = __float2bfloat16_rn(f);
    l = __float2bfloat16_rn(f - __bfloat162float(h));
}

// ---------------------------------------------------------------------------
// weight conversion: fp32 -> bf16 hi/lo (grid-stride over float4s)
// ---------------------------------------------------------------------------
__global__ void conv_w(const float* __restrict__ src,
                       __nv_bfloat16* __restrict__ hi,
                       __nv_bfloat16* __restrict__ lo, int n4) {
    int i = blockIdx.x * blockDim.x + threadIdx.x;
    const int stride = gridDim.x * blockDim.x;
    for (; i < n4; i += stride) {
        float4 v = ((const float4*)src)[i];
        float f[4] = { v.x, v.y, v.z, v.w };
        uint32_t hp[2], lp[2];
        #pragma unroll
        for (int q = 0; q < 2; q++) {
            __nv_bfloat16 h0, l0, h1, l1;
            split_bf(f[2*q],   h0, l0);
            split_bf(f[2*q+1], h1, l1);
            hp[q] = (uint32_t)__bfloat16_as_ushort(h0) | ((uint32_t)__bfloat16_as_ushort(h1) << 16);
            lp[q] = (uint32_t)__bfloat16_as_ushort(l0) | ((uint32_t)__bfloat16_as_ushort(l1) << 16);
        }
        ((uint2*)hi)[i] = make_uint2(hp[0], hp[1]);
        ((uint2*)lo)[i] = make_uint2(lp[0], lp[1]);
    }
}

// ---------------------------------------------------------------------------
// init: g_x[m,:] = hidden_states[b, j, :]
// ---------------------------------------------------------------------------
__global__ void init_h_kernel(const float* __restrict__ hidden, float* __restrict__ hbuf) {
    const int m = blockIdx.x;
    const int b = m >> 8, j = m & 255;
    const float* src = hidden + ((size_t)b * TT + j) * DD;
    float* dst = hbuf + (size_t)m * DD;
    #pragma unroll
    for (int i = 0; i < 4; i++) dst[threadIdx.x + i * 256] = src[threadIdx.x + i * 256];
}

// ---------------------------------------------------------------------------
// prep: xc_hi/lo[m, half*1024 + :] = bf16split(rms(src))
// ---------------------------------------------------------------------------
__global__ void prep_kernel(const int* __restrict__ tok,
                            const float* __restrict__ emb,
                            const float* __restrict__ hprev,
                            const float* __restrict__ rms_w,
                            __nv_bfloat16* __restrict__ xch,
                            __nv_bfloat16* __restrict__ xcl, int h) {
    const int m = blockIdx.x;
    const int half = blockIdx.y;
    const int tid = threadIdx.x;
    const int b = m >> 8, j = m & 255;
    const float* src;
    if (half == 0) {
        const int t = tok[b * TT + 1 + h + j];
        src = emb + (size_t)t * DD;
    } else {
        src = hprev + (size_t)m * DD;
    }
    float v[4];
    float ss = 0.0f;
    #pragma unroll
    for (int i = 0; i < 4; i++) { v[i] = src[tid + i * 256]; ss += v[i] * v[i]; }
    ss = block_sum(ss);
    const float s = rsqrtf(ss * (1.0f / DD) + 1e-6f);
    const size_t base = (size_t)m * (2 * DD) + half * DD;
    #pragma unroll
    for (int i = 0; i < 4; i++) {
        const int d = tid + i * 256;
        const float f = v[i] * s * rms_w[d];
        __nv_bfloat16 hh, ll;
        split_bf(f, hh, ll);
        xch[base + d] = hh;
        xcl[base + d] = ll;
    }
}

// ---------------------------------------------------------------------------
// residual + LN (in place on x fp32) + bf16 hi/lo output
// ---------------------------------------------------------------------------
__global__ void resid_ln_kernel(float* __restrict__ x, const float* __restrict__ u,
                                const float* __restrict__ w, const float* __restrict__ bb,
                                __nv_bfloat16* __restrict__ oh, __nv_bfloat16* __restrict__ ol) {
    const int m = blockIdx.x;
    const int tid = threadIdx.x;
    float* xr = x + (size_t)m * DD;
    const float* ur = u + (size_t)m * DD;
    float v[4];
    float s = 0.0f;
    #pragma unroll
    for (int i = 0; i < 4; i++) {
        v[i] = xr[tid + i * 256] + ur[tid + i * 256];
        s += v[i];
    }
    s = block_sum(s);
    const float mu = s * (1.0f / DD);
    float s2 = 0.0f;
    #pragma unroll
    for (int i = 0; i < 4; i++) { const float d = v[i] - mu; s2 += d * d; }
    s2 = block_sum(s2);
    const float rs = rsqrtf(s2 * (1.0f / DD) + 1e-5f);
    #pragma unroll
    for (int i = 0; i < 4; i++) {
        const int d = tid + i * 256;
        const float f = (v[i] - mu) * rs * w[d] + bb[d];
        xr[d] = f;
        __nv_bfloat16 hh, ll;
        split_bf(f, hh, ll);
        oh[(size_t)m * DD + d] = hh;
        ol[(size_t)m * DD + d] = ll;
    }
}

// ---------------------------------------------------------------------------
// bf16 split-precision GEMM, all-bf16 operands, cp.async 3-stage pipeline.
// C[m,n] = sum_k (Ahi+Alo)[m,k]*(Bhi+Blo)[n,k] + bias[n]  (3-product emu)
// A: [M][K] bf16 RM (hi/lo), B: [N][K] bf16 RM (hi/lo).
// Outputs: optional fp32 C (ldc), optional bf16 hi/lo O (ldo).
// ---------------------------------------------------------------------------
template<int BM, int BN, int WGN>
__global__ void __launch_bounds__(256) gemm_bf(
    const __nv_bfloat16* __restrict__ Ahi, const __nv_bfloat16* __restrict__ Alo,
    const __nv_bfloat16* __restrict__ Bhi, const __nv_bfloat16* __restrict__ Blo,
    const float* __restrict__ bias,
    float* __restrict__ C, long long ldc,
    __nv_bfloat16* __restrict__ Ohi, __nv_bfloat16* __restrict__ Olo, int ldo,
    int K, int relu)
{
    constexpr int WGM = 8 / WGN;
    constexpr int WM  = BM / WGM;
    constexpr int WN  = BN / WGN;
    constexpr int MI  = WM / 16;
    constexpr int NI  = WN / 8;
    constexpr int LS  = 40;                 // padded elems/row (80B, 16B-mult)
    constexpr int AT  = BM * LS * 2;        // bytes per tile
    constexpr int BT  = BN * LS * 2;
    constexpr int STAGE = 2 * AT + 2 * BT;
    constexpr int S   = 3;

    extern __shared__ char smem[];
    const uint32_t sb = s2u(smem);

    const int tid  = threadIdx.x;
    const int wid  = tid >> 5;
    const int lane = tid & 31;
    const int wm   = wid / WGN;
    const int wn   = wid % WGN;
    const int m0   = blockIdx.x * BM;
    const int n0   = blockIdx.y * BN;
    const int nCh  = K >> 5;

    float acc[MI][NI][4];
    #pragma unroll
    for (int i = 0; i < MI; i++)
        #pragma unroll
        for (int j = 0; j < NI; j++)
            #pragma unroll
            for (int q = 0; q < 4; q++) acc[i][j][q] = 0.0f;

    // ---- async stage issue
    auto issue = [&](int c) {
        if (c < nCh) {
            const int k0 = c << 5;
            const uint32_t st = sb + (uint32_t)(c % S) * STAGE;
            #pragma unroll
            for (int q = tid; q < BM * 4; q += 256) {
                const int row = q >> 2, col = (q & 3) << 3;
                const size_t off = (size_t)(m0 + row) * K + k0 + col;
                const uint32_t d = st + (uint32_t)(row * LS + col) * 2u;
                asm volatile("cp.async.cg.shared.global [%0], [%1], 16;" :: "r"(d), "l"(Ahi + off));
                asm volatile("cp.async.cg.shared.global [%0], [%1], 16;" :: "r"(d + AT), "l"(Alo + off));
            }
            #pragma unroll
            for (int q = tid; q < BN * 4; q += 256) {
                const int row = q >> 2, col = (q & 3) << 3;
                const size_t off = (size_t)(n0 + row) * K + k0 + col;
                const uint32_t d = st + 2 * AT + (uint32_t)(row * LS + col) * 2u;
                asm volatile("cp.async.cg.shared.global [%0], [%1], 16;" :: "r"(d), "l"(Bhi + off));
                asm volatile("cp.async.cg.shared.global [%0], [%1], 16;" :: "r"(d + BT), "l"(Blo + off));
            }
        }
        asm volatile("cp.async.commit_group;" ::: "memory");
    };

    issue(0);
    issue(1);

    for (int c = 0; c < nCh; c++) {
        asm volatile("cp.async.wait_group 1;" ::: "memory");
        __syncthreads();
        issue(c + 2);

        const uint32_t st  = sb + (uint32_t)(c % S) * STAGE;
        const uint32_t sAh = st;
        const uint32_t sBh = st + 2 * AT;
        #pragma unroll
        for (int ks = 0; ks < 2; ks++) {
            uint32_t ah[MI][4], al[MI][4];
            #pragma unroll
            for (int mi = 0; mi < MI; mi++) {
                const int row = wm * WM + mi * 16 + (lane & 15);
                const int col = ks * 16 + (lane >> 4) * 8;
                const uint32_t ad = sAh + (uint32_t)(row * LS + col) * 2u;
                ldsm4(ah[mi], ad);
                ldsm4(al[mi], ad + AT);
            }
            uint32_t bh[NI][2], bl[NI][2];
            #pragma unroll
            for (int ni = 0; ni < NI; ni += 2) {
                const int g = lane >> 3;
                const int row = wn * WN + ni * 8 + ((g >> 1) << 3) + (lane & 7);
                const int col = ks * 16 + ((g & 1) << 3);
                const uint32_t bd = sBh + (uint32_t)(row * LS + col) * 2u;
                ldsm4(&bh[ni][0], bd);
                ldsm4(&bl[ni][0], bd + BT);
            }
            #pragma unroll
            for (int mi = 0; mi < MI; mi++)
                #pragma unroll
                for (int ni = 0; ni < NI; ni++)
                    mma_bf16(acc[mi][ni], ah[mi], bh[ni]);
            #pragma unroll
            for (int mi = 0; mi < MI; mi++)
                #pragma unroll
                for (int ni = 0; ni < NI; ni++)
                    mma_bf16(acc[mi][ni], ah[mi], bl[ni]);
            #pragma unroll
            for (int mi = 0; mi < MI; mi++)
                #pragma unroll
                for (int ni = 0; ni < NI; ni++)
                    mma_bf16(acc[mi][ni], al[mi], bh[ni]);
        }
    }

    // ---- epilogue
    #pragma unroll
    for (int mi = 0; mi < MI; mi++) {
        #pragma unroll
        for (int ni = 0; ni < NI; ni++) {
            const int r0 = m0 + wm * WM + mi * 16 + (lane >> 2);
            const int cc = n0 + wn * WN + ni * 8 + ((lane & 3) << 1);
            const float b0 = bias[cc], b1 = bias[cc + 1];
            float v0 = acc[mi][ni][0] + b0;
            float v1 = acc[mi][ni][1] + b1;
            float v2 = acc[mi][ni][2] + b0;
            float v3 = acc[mi][ni][3] + b1;
            if (relu) {
                v0 = fmaxf(v0, 0.0f); v1 = fmaxf(v1, 0.0f);
                v2 = fmaxf(v2, 0.0f); v3 = fmaxf(v3, 0.0f);
            }
            if (C) {
                *(float2*)(C + (size_t)r0 * (size_t)ldc + cc)       = make_float2(v0, v1);
                *(float2*)(C + (size_t)(r0 + 8) * (size_t)ldc + cc) = make_float2(v2, v3);
            }
            if (Ohi) {
                __nv_bfloat16 h0, l0, h1, l1, h2, l2, h3, l3;
                split_bf(v0, h0, l0); split_bf(v1, h1, l1);
                split_bf(v2, h2, l2); split_bf(v3, h3, l3);
                *(uint32_t*)(Ohi + (size_t)r0 * ldo + cc) =
                    (uint32_t)__bfloat16_as_ushort(h0) | ((uint32_t)__bfloat16_as_ushort(h1) << 16);
                *(uint32_t*)(Olo + (size_t)r0 * ldo + cc) =
                    (uint32_t)__bfloat16_as_ushort(l0) | ((uint32_t)__bfloat16_as_ushort(l1) << 16);
                *(uint32_t*)(Ohi + (size_t)(r0 + 8) * ldo + cc) =
                    (uint32_t)__bfloat16_as_ushort(h2) | ((uint32_t)__bfloat16_as_ushort(h3) << 16);
                *(uint32_t*)(Olo + (size_t)(r0 + 8) * ldo + cc) =
                    (uint32_t)__bfloat16_as_ushort(l2) | ((uint32_t)__bfloat16_as_ushort(l3) << 16);
            }
        }
    }
}

// SMEM per config (3 stages)
#define SMEM_SMALL (3 * (2 * 64 * 40 * 2 + 2 * 64 * 40 * 2))     // 61440
#define SMEM_BIG   (3 * (2 * 128 * 40 * 2 + 2 * 128 * 40 * 2))   // 122880

// ---------------------------------------------------------------------------
// Host orchestration
// ---------------------------------------------------------------------------
extern "C" void kernel_launch(void* const* d_in, const int* in_sizes, int n_in,
                              void* d_out, int out_size) {
    const int*   tok     = (const int*)  d_in[0];
    const float* hidden  = (const float*)d_in[1];
    const float* emb     = (const float*)d_in[2];
    const float* rms_w   = (const float*)d_in[3];
    const float* proj_w  = (const float*)d_in[4];
    const float* proj_b  = (const float*)d_in[5];
    const float* sa_wv   = (const float*)d_in[6];
    const float* sa_bv   = (const float*)d_in[7];
    const float* sa_wo   = (const float*)d_in[8];
    const float* sa_bo   = (const float*)d_in[9];
    const float* ca_wv   = (const float*)d_in[10];
    const float* ca_bv   = (const float*)d_in[11];
    const float* ca_wo   = (const float*)d_in[12];
    const float* ca_bo   = (const float*)d_in[13];
    const float* ln1_w   = (const float*)d_in[14];
    const float* ln1_b   = (const float*)d_in[15];
    const float* ln2_w   = (const float*)d_in[16];
    const float* ln2_b   = (const float*)d_in[17];
    const float* ln3_w   = (const float*)d_in[18];
    const float* ln3_b   = (const float*)d_in[19];
    const float* ff_w1   = (const float*)d_in[20];
    const float* ff_b1   = (const float*)d_in[21];
    const float* ff_w2   = (const float*)d_in[22];
    const float* ff_b2   = (const float*)d_in[23];
    const float* unemb_w = (const float*)d_in[24];
    const float* unemb_b = (const float*)d_in[25];
    float* out = (float*)d_out;

    static __nv_bfloat16 *whi = nullptr, *wlo = nullptr;
    static __nv_bfloat16 *xch = nullptr, *xcl = nullptr, *xh = nullptr, *xl = nullptr;
    static __nv_bfloat16 *t1h = nullptr, *t1l = nullptr;
    static float *x = nullptr, *t2 = nullptr;
    static bool attr_done = false;
    if (!whi) {
        cudaGetSymbolAddress((void**)&whi, g_whi);
        cudaGetSymbolAddress((void**)&wlo, g_wlo);
        cudaGetSymbolAddress((void**)&xch, g_xc_hi);
        cudaGetSymbolAddress((void**)&xcl, g_xc_lo);
        cudaGetSymbolAddress((void**)&xh,  g_x_hi);
        cudaGetSymbolAddress((void**)&xl,  g_x_lo);
        cudaGetSymbolAddress((void**)&t1h, g_t1_hi);
        cudaGetSymbolAddress((void**)&t1l, g_t1_lo);
        cudaGetSymbolAddress((void**)&x,   g_x);
        cudaGetSymbolAddress((void**)&t2,  g_t2);
    }
    if (!attr_done) {
        cudaFuncSetAttribute(gemm_bf<64, 64, 4>,
                             cudaFuncAttributeMaxDynamicSharedMemorySize, SMEM_SMALL);
        cudaFuncSetAttribute(gemm_bf<128, 128, 2>,
                             cudaFuncAttributeMaxDynamicSharedMemorySize, SMEM_BIG);
        attr_done = true;
    }

    // ---- one-time-per-launch weight conversion
    conv_w<<<1024, 256>>>(proj_w,  whi + OFF_PROJ, wlo + OFF_PROJ, 8388608 / 4);
    conv_w<<<1024, 256>>>(sa_wv,   whi + OFF_SAWV, wlo + OFF_SAWV, 4194304 / 4);
    conv_w<<<1024, 256>>>(sa_wo,   whi + OFF_SAWO, wlo + OFF_SAWO, 4194304 / 4);
    conv_w<<<1024, 256>>>(ca_wv,   whi + OFF_CAWV, wlo + OFF_CAWV, 4194304 / 4);
    conv_w<<<1024, 256>>>(ca_wo,   whi + OFF_CAWO, wlo + OFF_CAWO, 4194304 / 4);
    conv_w<<<1024, 256>>>(ff_w1,   whi + OFF_FF1,  wlo + OFF_FF1,  8388608 / 4);
    conv_w<<<1024, 256>>>(ff_w2,   whi + OFF_FF2,  wlo + OFF_FF2,  8388608 / 4);
    conv_w<<<2048, 256>>>(unemb_w, whi + OFF_UNE,  wlo + OFF_UNE, 32768000 / 4);

    init_h_kernel<<<MM, 256>>>(hidden, x);

    for (int h = 0; h < HH; h++) {
        // xc = bf16split(concat(rms(e), rms(h_prev)))
        prep_kernel<<<dim3(MM, 2), 256>>>(tok, emb, x, rms_w, xch, xcl, h);

        // x = xc @ proj_w[h]^T + proj_b[h]   (512 x 1024 x 2048), fp32 + bf16 out
        gemm_bf<64, 64, 4><<<dim3(MM / 64, DD / 64), 256, SMEM_SMALL>>>(
            xch, xcl, whi + OFF_PROJ + (size_t)h * 2097152, wlo + OFF_PROJ + (size_t)h * 2097152,
            proj_b + (size_t)h * DD, x, DD, xh, xl, DD, 2 * DD, 0);

        // t1 = x @ sa_wv^T (bf16 out only); t2 = t1 @ sa_wo^T (fp32)
        gemm_bf<64, 64, 4><<<dim3(MM / 64, DD / 64), 256, SMEM_SMALL>>>(
            xh, xl, whi + OFF_SAWV + (size_t)h * 1048576, wlo + OFF_SAWV + (size_t)h * 1048576,
            sa_bv + (size_t)h * DD, nullptr, 0, t1h, t1l, DD, DD, 0);
        gemm_bf<64, 64, 4><<<dim3(MM / 64, DD / 64), 256, SMEM_SMALL>>>(
            t1h, t1l, whi + OFF_SAWO + (size_t)h * 1048576, wlo + OFF_SAWO + (size_t)h * 1048576,
            sa_bo + (size_t)h * DD, t2, DD, nullptr, nullptr, 0, DD, 0);
        resid_ln_kernel<<<MM, 256>>>(x, t2, ln1_w + (size_t)h * DD, ln1_b + (size_t)h * DD, xh, xl);

        gemm_bf<64, 64, 4><<<dim3(MM / 64, DD / 64), 256, SMEM_SMALL>>>(
            xh, xl, whi + OFF_CAWV + (size_t)h * 1048576, wlo + OFF_CAWV + (size_t)h * 1048576,
            ca_bv + (size_t)h * DD, nullptr, 0, t1h, t1l, DD, DD, 0);
        gemm_bf<64, 64, 4><<<dim3(MM / 64, DD / 64), 256, SMEM_SMALL>>>(
            t1h, t1l, whi + OFF_CAWO + (size_t)h * 1048576, wlo + OFF_CAWO + (size_t)h * 1048576,
            ca_bo + (size_t)h * DD, t2, DD, nullptr, nullptr, 0, DD, 0);
        resid_ln_kernel<<<MM, 256>>>(x, t2, ln2_w + (size_t)h * DD, ln2_b + (size_t)h * DD, xh, xl);

        // FFN
        gemm_bf<64, 64, 4><<<dim3(MM / 64, DFF / 64), 256, SMEM_SMALL>>>(
            xh, xl, whi + OFF_FF1 + (size_t)h * 2097152, wlo + OFF_FF1 + (size_t)h * 2097152,
            ff_b1 + (size_t)h * DFF, nullptr, 0, t1h, t1l, DFF, DD, 1);
        gemm_bf<64, 64, 4><<<dim3(MM / 64, DD / 64), 256, SMEM_SMALL>>>(
            t1h, t1l, whi + OFF_FF2 + (size_t)h * 2097152, wlo + OFF_FF2 + (size_t)h * 2097152,
            ff_b2 + (size_t)h * DD, t2, DD, nullptr, nullptr, 0, DFF, 0);
        resid_ln_kernel<<<MM, 256>>>(x, t2, ln3_w + (size_t)h * DD, ln3_b + (size_t)h * DD, xh, xl);

        // logits (512 x 32000 x 1024) -> d_out, ldc = H*V
        gemm_bf<128, 128, 2><<<dim3(MM / 128, VV / 128), 256, SMEM_BIG>>>(
            xh, xl, whi + OFF_UNE, wlo + OFF_UNE,
            unemb_b, out + (size_t)h * VV, (long long)HH * VV, nullptr, nullptr, 0, DD, 0);
    }
}

// round 7
// speedup vs baseline: 2.9356x; 1.0797x over previous
#include <cuda_runtime.h>
#include <cuda_bf16.h>
#include <cstdint>

// Problem constants
#define BB   2
#define TT   260
#define HH   4
#define DD   1024
#define VV   32000
#define DFF  2048
#define MM   512

// ---------------------------------------------------------------------------
// Persistent scratch (__device__ globals; no allocations allowed)
// ---------------------------------------------------------------------------
#define OFF_PROJ 0
#define OFF_SAWV 8388608
#define OFF_SAWO 12582912
#define OFF_CAWV 16777216
#define OFF_CAWO 20971520
#define OFF_FF1  25165824
#define OFF_FF2  33554432
#define OFF_UNE  41943040
#define W_TOTAL  74711040

__device__ __nv_bfloat16 g_whi[W_TOTAL];
__device__ __nv_bfloat16 g_wlo[W_TOTAL];

__device__ float g_x  [MM * DD];
__device__ float g_t2 [MM * DD];
__device__ __nv_bfloat16 g_xc_hi[MM * 2 * DD], g_xc_lo[MM * 2 * DD];
__device__ __nv_bfloat16 g_x_hi [2][MM * DD],  g_x_lo [2][MM * DD];  // parity-buffered
__device__ __nv_bfloat16 g_t1_hi[MM * DFF],    g_t1_lo[MM * DFF];

// ---------------------------------------------------------------------------
// helpers
// ---------------------------------------------------------------------------
__device__ __forceinline__ float block_sum(float v) {
    __shared__ float sh[32];
    const int lane = threadIdx.x & 31;
    const int wid  = threadIdx.x >> 5;
    #pragma unroll
    for (int o = 16; o; o >>= 1) v += __shfl_xor_sync(0xffffffffu, v, o);
    if (lane == 0) sh[wid] = v;
    __syncthreads();
    if (wid == 0) {
        v = (lane < 8) ? sh[lane] : 0.0f;
        #pragma unroll
        for (int o = 4; o; o >>= 1) v += __shfl_xor_sync(0xffffffffu, v, o);
        if (lane == 0) sh[0] = v;
    }
    __syncthreads();
    v = sh[0];
    __syncthreads();
    return v;
}

__device__ __forceinline__ uint32_t s2u(const void* p) {
    uint32_t a;
    asm("{ .reg .u64 t; cvta.to.shared.u64 t, %1; cvt.u32.u64 %0, t; }" : "=r"(a) : "l"(p));
    return a;
}
__device__ __forceinline__ void ldsm4(uint32_t* r, uint32_t addr) {
    asm volatile("ldmatrix.sync.aligned.m8n8.x4.shared.b16 {%0,%1,%2,%3}, [%4];"
                 : "=r"(r[0]), "=r"(r[1]), "=r"(r[2]), "=r"(r[3]) : "r"(addr));
}
__device__ __forceinline__ void mma_bf16(float* c, const uint32_t* a, const uint32_t* b) {
    asm volatile(
        "mma.sync.aligned.m16n8k16.row.col.f32.bf16.bf16.f32 "
        "{%0,%1,%2,%3}, {%4,%5,%6,%7}, {%8,%9}, {%0,%1,%2,%3};"
        : "+f"(c[0]), "+f"(c[1]), "+f"(c[2]), "+f"(c[3])
        : "r"(a[0]), "r"(a[1]), "r"(a[2]), "r"(a[3]), "r"(b[0]), "r"(b[1]));
}
__device__ __forceinline__ void split_bf(float f, __nv_bfloat16& h, __nv_bfloat16& l) {
    h = __float2bfloat16_rn(f);
    l = __float2bfloat16_rn(f - __bfloat162float(h));
}

// ---------------------------------------------------------------------------
// weight conversion: fp32 -> bf16 hi/lo
// ---------------------------------------------------------------------------
__global__ void conv_w(const float* __restrict__ src,
                       __nv_bfloat16* __restrict__ hi,
                       __nv_bfloat16* __restrict__ lo, int n4) {
    int i = blockIdx.x * blockDim.x + threadIdx.x;
    const int stride = gridDim.x * blockDim.x;
    for (; i < n4; i += stride) {
        float4 v = ((const float4*)src)[i];
        float f[4] = { v.x, v.y, v.z, v.w };
        uint32_t hp[2], lp[2];
        #pragma unroll
        for (int q = 0; q < 2; q++) {
            __nv_bfloat16 h0, l0, h1, l1;
            split_bf(f[2*q],   h0, l0);
            split_bf(f[2*q+1], h1, l1);
            hp[q] = (uint32_t)__bfloat16_as_ushort(h0) | ((uint32_t)__bfloat16_as_ushort(h1) << 16);
            lp[q] = (uint32_t)__bfloat16_as_ushort(l0) | ((uint32_t)__bfloat16_as_ushort(l1) << 16);
        }
        ((uint2*)hi)[i] = make_uint2(hp[0], hp[1]);
        ((uint2*)lo)[i] = make_uint2(lp[0], lp[1]);
    }
}

__global__ void init_h_kernel(const float* __restrict__ hidden, float* __restrict__ hbuf) {
    const int m = blockIdx.x;
    const int b = m >> 8, j = m & 255;
    const float* src = hidden + ((size_t)b * TT + j) * DD;
    float* dst = hbuf + (size_t)m * DD;
    #pragma unroll
    for (int i = 0; i < 4; i++) dst[threadIdx.x + i * 256] = src[threadIdx.x + i * 256];
}

__global__ void prep_kernel(const int* __restrict__ tok,
                            const float* __restrict__ emb,
                            const float* __restrict__ hprev,
                            const float* __restrict__ rms_w,
                            __nv_bfloat16* __restrict__ xch,
                            __nv_bfloat16* __restrict__ xcl, int h) {
    const int m = blockIdx.x;
    const int half = blockIdx.y;
    const int tid = threadIdx.x;
    const int b = m >> 8, j = m & 255;
    const float* src;
    if (half == 0) {
        const int t = tok[b * TT + 1 + h + j];
        src = emb + (size_t)t * DD;
    } else {
        src = hprev + (size_t)m * DD;
    }
    float v[4];
    float ss = 0.0f;
    #pragma unroll
    for (int i = 0; i < 4; i++) { v[i] = src[tid + i * 256]; ss += v[i] * v[i]; }
    ss = block_sum(ss);
    const float s = rsqrtf(ss * (1.0f / DD) + 1e-6f);
    const size_t base = (size_t)m * (2 * DD) + half * DD;
    #pragma unroll
    for (int i = 0; i < 4; i++) {
        const int d = tid + i * 256;
        const float f = v[i] * s * rms_w[d];
        __nv_bfloat16 hh, ll;
        split_bf(f, hh, ll);
        xch[base + d] = hh;
        xcl[base + d] = ll;
    }
}

__global__ void resid_ln_kernel(float* __restrict__ x, const float* __restrict__ u,
                                const float* __restrict__ w, const float* __restrict__ bb,
                                __nv_bfloat16* __restrict__ oh, __nv_bfloat16* __restrict__ ol) {
    const int m = blockIdx.x;
    const int tid = threadIdx.x;
    float* xr = x + (size_t)m * DD;
    const float* ur = u + (size_t)m * DD;
    float v[4];
    float s = 0.0f;
    #pragma unroll
    for (int i = 0; i < 4; i++) {
        v[i] = xr[tid + i * 256] + ur[tid + i * 256];
        s += v[i];
    }
    s = block_sum(s);
    const float mu = s * (1.0f / DD);
    float s2 = 0.0f;
    #pragma unroll
    for (int i = 0; i < 4; i++) { const float d = v[i] - mu; s2 += d * d; }
    s2 = block_sum(s2);
    const float rs = rsqrtf(s2 * (1.0f / DD) + 1e-5f);
    #pragma unroll
    for (int i = 0; i < 4; i++) {
        const int d = tid + i * 256;
        const float f = (v[i] - mu) * rs * w[d] + bb[d];
        xr[d] = f;
        __nv_bfloat16 hh, ll;
        split_bf(f, hh, ll);
        oh[(size_t)m * DD + d] = hh;
        ol[(size_t)m * DD + d] = ll;
    }
}

// ---------------------------------------------------------------------------
// bf16 split-precision GEMM (3-product emulation), cp.async 3-stage pipeline.
// ---------------------------------------------------------------------------
template<int BM, int BN, int WGM, int WGN, int NTH>
__global__ void __launch_bounds__(NTH) gemm_bf(
    const __nv_bfloat16* __restrict__ Ahi, const __nv_bfloat16* __restrict__ Alo,
    const __nv_bfloat16* __restrict__ Bhi, const __nv_bfloat16* __restrict__ Blo,
    const float* __restrict__ bias,
    float* __restrict__ C, long long ldc,
    __nv_bfloat16* __restrict__ Ohi, __nv_bfloat16* __restrict__ Olo, int ldo,
    int K, int relu)
{
    constexpr int WM  = BM / WGM;
    constexpr int WN  = BN / WGN;
    constexpr int MI  = WM / 16;
    constexpr int NI  = WN / 8;
    constexpr int LS  = 40;
    constexpr int AT  = BM * LS * 2;
    constexpr int BT  = BN * LS * 2;
    constexpr int STAGE = 2 * AT + 2 * BT;
    constexpr int S   = 3;

    extern __shared__ char smem[];
    const uint32_t sb = s2u(smem);

    const int tid  = threadIdx.x;
    const int wid  = tid >> 5;
    const int lane = tid & 31;
    const int wm   = wid / WGN;
    const int wn   = wid % WGN;
    const int m0   = blockIdx.x * BM;
    const int n0   = blockIdx.y * BN;
    const int nCh  = K >> 5;

    float acc[MI][NI][4];
    #pragma unroll
    for (int i = 0; i < MI; i++)
        #pragma unroll
        for (int j = 0; j < NI; j++)
            #pragma unroll
            for (int q = 0; q < 4; q++) acc[i][j][q] = 0.0f;

    auto issue = [&](int c) {
        if (c < nCh) {
            const int k0 = c << 5;
            const uint32_t st = sb + (uint32_t)(c % S) * STAGE;
            #pragma unroll
            for (int q = tid; q < BM * 4; q += NTH) {
                const int row = q >> 2, col = (q & 3) << 3;
                const size_t off = (size_t)(m0 + row) * K + k0 + col;
                const uint32_t d = st + (uint32_t)(row * LS + col) * 2u;
                asm volatile("cp.async.cg.shared.global [%0], [%1], 16;" :: "r"(d), "l"(Ahi + off));
                asm volatile("cp.async.cg.shared.global [%0], [%1], 16;" :: "r"(d + AT), "l"(Alo + off));
            }
            #pragma unroll
            for (int q = tid; q < BN * 4; q += NTH) {
                const int row = q >> 2, col = (q & 3) << 3;
                const size_t off = (size_t)(n0 + row) * K + k0 + col;
                const uint32_t d = st + 2 * AT + (uint32_t)(row * LS + col) * 2u;
                asm volatile("cp.async.cg.shared.global [%0], [%1], 16;" :: "r"(d), "l"(Bhi + off));
                asm volatile("cp.async.cg.shared.global [%0], [%1], 16;" :: "r"(d + BT), "l"(Blo + off));
            }
        }
        asm volatile("cp.async.commit_group;" ::: "memory");
    };

    issue(0);
    issue(1);

    for (int c = 0; c < nCh; c++) {
        asm volatile("cp.async.wait_group 1;" ::: "memory");
        __syncthreads();
        issue(c + 2);

        const uint32_t st  = sb + (uint32_t)(c % S) * STAGE;
        const uint32_t sAh = st;
        const uint32_t sBh = st + 2 * AT;
        #pragma unroll
        for (int ks = 0; ks < 2; ks++) {
            uint32_t ah[MI][4], al[MI][4];
            #pragma unroll
            for (int mi = 0; mi < MI; mi++) {
                const int row = wm * WM + mi * 16 + (lane & 15);
                const int col = ks * 16 + (lane >> 4) * 8;
                const uint32_t ad = sAh + (uint32_t)(row * LS + col) * 2u;
                ldsm4(ah[mi], ad);
                ldsm4(al[mi], ad + AT);
            }
            uint32_t bh[NI][2], bl[NI][2];
            #pragma unroll
            for (int ni = 0; ni < NI; ni += 2) {
                const int g = lane >> 3;
                const int row = wn * WN + ni * 8 + ((g >> 1) << 3) + (lane & 7);
                const int col = ks * 16 + ((g & 1) << 3);
                const uint32_t bd = sBh + (uint32_t)(row * LS + col) * 2u;
                ldsm4(&bh[ni][0], bd);
                ldsm4(&bl[ni][0], bd + BT);
            }
            #pragma unroll
            for (int mi = 0; mi < MI; mi++)
                #pragma unroll
                for (int ni = 0; ni < NI; ni++)
                    mma_bf16(acc[mi][ni], ah[mi], bh[ni]);
            #pragma unroll
            for (int mi = 0; mi < MI; mi++)
                #pragma unroll
                for (int ni = 0; ni < NI; ni++)
                    mma_bf16(acc[mi][ni], ah[mi], bl[ni]);
            #pragma unroll
            for (int mi = 0; mi < MI; mi++)
                #pragma unroll
                for (int ni = 0; ni < NI; ni++)
                    mma_bf16(acc[mi][ni], al[mi], bh[ni]);
        }
    }

    #pragma unroll
    for (int mi = 0; mi < MI; mi++) {
        #pragma unroll
        for (int ni = 0; ni < NI; ni++) {
            const int r0 = m0 + wm * WM + mi * 16 + (lane >> 2);
            const int cc = n0 + wn * WN + ni * 8 + ((lane & 3) << 1);
            const float b0 = bias[cc], b1 = bias[cc + 1];
            float v0 = acc[mi][ni][0] + b0;
            float v1 = acc[mi][ni][1] + b1;
            float v2 = acc[mi][ni][2] + b0;
            float v3 = acc[mi][ni][3] + b1;
            if (relu) {
                v0 = fmaxf(v0, 0.0f); v1 = fmaxf(v1, 0.0f);
                v2 = fmaxf(v2, 0.0f); v3 = fmaxf(v3, 0.0f);
            }
            if (C) {
                *(float2*)(C + (size_t)r0 * (size_t)ldc + cc)       = make_float2(v0, v1);
                *(float2*)(C + (size_t)(r0 + 8) * (size_t)ldc + cc) = make_float2(v2, v3);
            }
            if (Ohi) {
                __nv_bfloat16 h0, l0, h1, l1, h2, l2, h3, l3;
                split_bf(v0, h0, l0); split_bf(v1, h1, l1);
                split_bf(v2, h2, l2); split_bf(v3, h3, l3);
                *(uint32_t*)(Ohi + (size_t)r0 * ldo + cc) =
                    (uint32_t)__bfloat16_as_ushort(h0) | ((uint32_t)__bfloat16_as_ushort(h1) << 16);
                *(uint32_t*)(Olo + (size_t)r0 * ldo + cc) =
                    (uint32_t)__bfloat16_as_ushort(l0) | ((uint32_t)__bfloat16_as_ushort(l1) << 16);
                *(uint32_t*)(Ohi + (size_t)(r0 + 8) * ldo + cc) =
                    (uint32_t)__bfloat16_as_ushort(h2) | ((uint32_t)__bfloat16_as_ushort(h3) << 16);
                *(uint32_t*)(Olo + (size_t)(r0 + 8) * ldo + cc) =
                    (uint32_t)__bfloat16_as_ushort(l2) | ((uint32_t)__bfloat16_as_ushort(l3) << 16);
            }
        }
    }
}

#define SMEM_SMALL (3 * (2 * 64 * 40 * 2 + 2 * 64 * 40 * 2))      // 61440
#define SMEM_UNE   (3 * (2 * 128 * 40 * 2 + 2 * 256 * 40 * 2))    // 184320

// ---------------------------------------------------------------------------
// Host orchestration (stream s2 runs unembed conversion + unembed GEMMs)
// ---------------------------------------------------------------------------
extern "C" void kernel_launch(void* const* d_in, const int* in_sizes, int n_in,
                              void* d_out, int out_size) {
    const int*   tok     = (const int*)  d_in[0];
    const float* hidden  = (const float*)d_in[1];
    const float* emb     = (const float*)d_in[2];
    const float* rms_w   = (const float*)d_in[3];
    const float* proj_w  = (const float*)d_in[4];
    const float* proj_b  = (const float*)d_in[5];
    const float* sa_wv   = (const float*)d_in[6];
    const float* sa_bv   = (const float*)d_in[7];
    const float* sa_wo   = (const float*)d_in[8];
    const float* sa_bo   = (const float*)d_in[9];
    const float* ca_wv   = (const float*)d_in[10];
    const float* ca_bv   = (const float*)d_in[11];
    const float* ca_wo   = (const float*)d_in[12];
    const float* ca_bo   = (const float*)d_in[13];
    const float* ln1_w   = (const float*)d_in[14];
    const float* ln1_b   = (const float*)d_in[15];
    const float* ln2_w   = (const float*)d_in[16];
    const float* ln2_b   = (const float*)d_in[17];
    const float* ln3_w   = (const float*)d_in[18];
    const float* ln3_b   = (const float*)d_in[19];
    const float* ff_w1   = (const float*)d_in[20];
    const float* ff_b1   = (const float*)d_in[21];
    const float* ff_w2   = (const float*)d_in[22];
    const float* ff_b2   = (const float*)d_in[23];
    const float* unemb_w = (const float*)d_in[24];
    const float* unemb_b = (const float*)d_in[25];
    float* out = (float*)d_out;

    static __nv_bfloat16 *whi = nullptr, *wlo = nullptr;
    static __nv_bfloat16 *xch = nullptr, *xcl = nullptr;
    static __nv_bfloat16 *xh[2] = {nullptr, nullptr}, *xl[2] = {nullptr, nullptr};
    static __nv_bfloat16 *t1h = nullptr, *t1l = nullptr;
    static float *x = nullptr, *t2 = nullptr;
    static cudaStream_t s2 = nullptr;
    static cudaEvent_t evStart = nullptr, evDone = nullptr, evH[HH] = {};
    if (!whi) {
        cudaGetSymbolAddress((void**)&whi, g_whi);
        cudaGetSymbolAddress((void**)&wlo, g_wlo);
        cudaGetSymbolAddress((void**)&xch, g_xc_hi);
        cudaGetSymbolAddress((void**)&xcl, g_xc_lo);
        {
            __nv_bfloat16* p;
            cudaGetSymbolAddress((void**)&p, g_x_hi);
            xh[0] = p; xh[1] = p + (size_t)MM * DD;
            cudaGetSymbolAddress((void**)&p, g_x_lo);
            xl[0] = p; xl[1] = p + (size_t)MM * DD;
        }
        cudaGetSymbolAddress((void**)&t1h, g_t1_hi);
        cudaGetSymbolAddress((void**)&t1l, g_t1_lo);
        cudaGetSymbolAddress((void**)&x,   g_x);
        cudaGetSymbolAddress((void**)&t2,  g_t2);
        cudaFuncSetAttribute(gemm_bf<64, 64, 2, 4, 256>,
                             cudaFuncAttributeMaxDynamicSharedMemorySize, SMEM_SMALL);
        cudaFuncSetAttribute(gemm_bf<128, 256, 4, 4, 512>,
                             cudaFuncAttributeMaxDynamicSharedMemorySize, SMEM_UNE);
        cudaStreamCreateWithFlags(&s2, cudaStreamNonBlocking);
        cudaEventCreateWithFlags(&evStart, cudaEventDisableTiming);
        cudaEventCreateWithFlags(&evDone,  cudaEventDisableTiming);
        for (int i = 0; i < HH; i++) cudaEventCreateWithFlags(&evH[i], cudaEventDisableTiming);
    }

    // fork s2 off the capture stream
    cudaEventRecord(evStart, 0);
    cudaStreamWaitEvent(s2, evStart, 0);

    // unembed weight conversion on s2 (only unembed consumes it)
    conv_w<<<2048, 256, 0, s2>>>(unemb_w, whi + OFF_UNE, wlo + OFF_UNE, 32768000 / 4);

    // chain weight conversions on main stream
    conv_w<<<1024, 256>>>(proj_w,  whi + OFF_PROJ, wlo + OFF_PROJ, 8388608 / 4);
    conv_w<<<1024, 256>>>(sa_wv,   whi + OFF_SAWV, wlo + OFF_SAWV, 4194304 / 4);
    conv_w<<<1024, 256>>>(sa_wo,   whi + OFF_SAWO, wlo + OFF_SAWO, 4194304 / 4);
    conv_w<<<1024, 256>>>(ca_wv,   whi + OFF_CAWV, wlo + OFF_CAWV, 4194304 / 4);
    conv_w<<<1024, 256>>>(ca_wo,   whi + OFF_CAWO, wlo + OFF_CAWO, 4194304 / 4);
    conv_w<<<1024, 256>>>(ff_w1,   whi + OFF_FF1,  wlo + OFF_FF1,  8388608 / 4);
    conv_w<<<1024, 256>>>(ff_w2,   whi + OFF_FF2,  wlo + OFF_FF2,  8388608 / 4);

    init_h_kernel<<<MM, 256>>>(hidden, x);

    for (int h = 0; h < HH; h++) {
        const int pb = h & 1;
        __nv_bfloat16 *XH = xh[pb], *XL = xl[pb];

        prep_kernel<<<dim3(MM, 2), 256>>>(tok, emb, x, rms_w, xch, xcl, h);

        gemm_bf<64, 64, 2, 4, 256><<<dim3(MM / 64, DD / 64), 256, SMEM_SMALL>>>(
            xch, xcl, whi + OFF_PROJ + (size_t)h * 2097152, wlo + OFF_PROJ + (size_t)h * 2097152,
            proj_b + (size_t)h * DD, x, DD, XH, XL, DD, 2 * DD, 0);

        gemm_bf<64, 64, 2, 4, 256><<<dim3(MM / 64, DD / 64), 256, SMEM_SMALL>>>(
            XH, XL, whi + OFF_SAWV + (size_t)h * 1048576, wlo + OFF_SAWV + (size_t)h * 1048576,
            sa_bv + (size_t)h * DD, nullptr, 0, t1h, t1l, DD, DD, 0);
        gemm_bf<64, 64, 2, 4, 256><<<dim3(MM / 64, DD / 64), 256, SMEM_SMALL>>>(
            t1h, t1l, whi + OFF_SAWO + (size_t)h * 1048576, wlo + OFF_SAWO + (size_t)h * 1048576,
            sa_bo + (size_t)h * DD, t2, DD, nullptr, nullptr, 0, DD, 0);
        resid_ln_kernel<<<MM, 256>>>(x, t2, ln1_w + (size_t)h * DD, ln1_b + (size_t)h * DD, XH, XL);

        gemm_bf<64, 64, 2, 4, 256><<<dim3(MM / 64, DD / 64), 256, SMEM_SMALL>>>(
            XH, XL, whi + OFF_CAWV + (size_t)h * 1048576, wlo + OFF_CAWV + (size_t)h * 1048576,
            ca_bv + (size_t)h * DD, nullptr, 0, t1h, t1l, DD, DD, 0);
        gemm_bf<64, 64, 2, 4, 256><<<dim3(MM / 64, DD / 64), 256, SMEM_SMALL>>>(
            t1h, t1l, whi + OFF_CAWO + (size_t)h * 1048576, wlo + OFF_CAWO + (size_t)h * 1048576,
            ca_bo + (size_t)h * DD, t2, DD, nullptr, nullptr, 0, DD, 0);
        resid_ln_kernel<<<MM, 256>>>(x, t2, ln2_w + (size_t)h * DD, ln2_b + (size_t)h * DD, XH, XL);

        gemm_bf<64, 64, 2, 4, 256><<<dim3(MM / 64, DFF / 64), 256, SMEM_SMALL>>>(
            XH, XL, whi + OFF_FF1 + (size_t)h * 2097152, wlo + OFF_FF1 + (size_t)h * 2097152,
            ff_b1 + (size_t)h * DFF, nullptr, 0, t1h, t1l, DFF, DD, 1);
        gemm_bf<64, 64, 2, 4, 256><<<dim3(MM / 64, DD / 64), 256, SMEM_SMALL>>>(
            t1h, t1l, whi + OFF_FF2 + (size_t)h * 2097152, wlo + OFF_FF2 + (size_t)h * 2097152,
            ff_b2 + (size_t)h * DD, t2, DD, nullptr, nullptr, 0, DFF, 0);
        resid_ln_kernel<<<MM, 256>>>(x, t2, ln3_w + (size_t)h * DD, ln3_b + (size_t)h * DD, XH, XL);

        // hand final activations of head h to stream s2 for the unembed GEMM
        cudaEventRecord(evH[h], 0);
        cudaStreamWaitEvent(s2, evH[h], 0);
        gemm_bf<128, 256, 4, 4, 512><<<dim3(MM / 128, VV / 256), 512, SMEM_UNE, s2>>>(
            XH, XL, whi + OFF_UNE, wlo + OFF_UNE,
            unemb_b, out + (size_t)h * VV, (long long)HH * VV, nullptr, nullptr, 0, DD, 0);
    }

    // join s2 back into the capture stream
    cudaEventRecord(evDone, s2);
    cudaStreamWaitEvent(0, evDone, 0);
}